// round 2
// baseline (speedup 1.0000x reference)
#include <cuda_runtime.h>

// Problem dims (fixed by the dataset)
#define Bb 64
#define Tt 512
#define Ii 256
#define Hh 512
#define Mm (Bb*Tt)   // 32768 rows

// Scratch (allocation-free rule: device globals)
__device__ __align__(16) float g_W1[Hh*Ii];        // 0.5 MB
__device__ __align__(16) float g_W2[Hh*Hh];        // 1 MB
__device__ __align__(16) float g_z1[Mm*Hh];        // 64 MB
__device__ __align__(16) float g_s1[Mm*Hh];        // 64 MB
__device__ __align__(16) float g_y2[Mm*Hh];        // 64 MB

// -------- extract center tap of conv weight: W[h,i] = conv_w[h,i,1] --------
__global__ void extract1_k(const float* __restrict__ src) {
    int i = blockIdx.x * blockDim.x + threadIdx.x;
    if (i < Hh*Ii) g_W1[i] = src[i*3 + 1];
}
__global__ void extract2_k(const float* __restrict__ src) {
    int i = blockIdx.x * blockDim.x + threadIdx.x;
    if (i < Hh*Hh) g_W2[i] = src[i*3 + 1];
}

// -------- SGEMM: C[M,512] = A[M,K] * B[512,K]^T (+ optional bias) --------
// Block tile: 128(M) x 64(N), KT=8, 256 threads, 8x4 per thread.
// Single accumulator per output element, serial ascending-k order (matches
// the cublas/XLA SGEMM accumulation order for bitwise-comparable sums).
template<int K, bool ADD_BIAS>
__device__ __forceinline__ void sgemm_body(
    const float* __restrict__ A, const float* __restrict__ Bm,
    const float* __restrict__ bias, float* __restrict__ C)
{
    constexpr int KT = 8;
    __shared__ float As[KT][132];
    __shared__ float Bs[KT][68];

    const int tid = threadIdx.x;          // 256
    const int tx  = tid & 15;             // N dir: 16 * 4 = 64
    const int ty  = tid >> 4;             // M dir: 16 * 8 = 128
    const int m0  = blockIdx.y * 128;
    const int n0  = blockIdx.x * 64;

    float acc[8][4];
    #pragma unroll
    for (int i = 0; i < 8; i++)
        #pragma unroll
        for (int j = 0; j < 4; j++) acc[i][j] = 0.f;

    for (int k0 = 0; k0 < K; k0 += KT) {
        {
            const int r = tid >> 1;
            const int c = (tid & 1) * 4;
            const float4 a4 = *(const float4*)&A[(size_t)(m0 + r) * K + k0 + c];
            As[c+0][r] = a4.x; As[c+1][r] = a4.y; As[c+2][r] = a4.z; As[c+3][r] = a4.w;
        }
        if (tid < 128) {
            const int r = tid >> 1;
            const int c = (tid & 1) * 4;
            const float4 b4 = *(const float4*)&Bm[(size_t)(n0 + r) * K + k0 + c];
            Bs[c+0][r] = b4.x; Bs[c+1][r] = b4.y; Bs[c+2][r] = b4.z; Bs[c+3][r] = b4.w;
        }
        __syncthreads();

        #pragma unroll
        for (int k = 0; k < KT; k++) {
            float ra[8], rb[4];
            #pragma unroll
            for (int i = 0; i < 8; i++) ra[i] = As[k][ty*8 + i];
            #pragma unroll
            for (int j = 0; j < 4; j++) rb[j] = Bs[k][tx*4 + j];
            #pragma unroll
            for (int i = 0; i < 8; i++)
                #pragma unroll
                for (int j = 0; j < 4; j++)
                    acc[i][j] += ra[i] * rb[j];
        }
        __syncthreads();
    }

    #pragma unroll
    for (int i = 0; i < 8; i++) {
        const int m = m0 + ty*8 + i;
        #pragma unroll
        for (int j = 0; j < 4; j++) {
            const int n = n0 + tx*4 + j;
            float v = acc[i][j];
            if (ADD_BIAS) v = v + bias[n];
            C[(size_t)m * Hh + n] = v;
        }
    }
}

__global__ void __launch_bounds__(256) sgemm1_k(const float* __restrict__ A,
                                                const float* __restrict__ bias) {
    sgemm_body<Ii, true>(A, g_W1, bias, g_z1);   // z1 = x@W1^T + b1 (one add, like ref)
}
__global__ void __launch_bounds__(256) sgemm2_k() {
    sgemm_body<Hh, false>(g_s1, g_W2, nullptr, g_y2);  // dot only; bias added in scan
}

// -------- LIF scan over t for 32768 independent (b,h) chains --------
// Layer 1 step (ref): m += z1_t; thr = m/th - 1; s = (thr >= 0); m -= th*(thr>0)
__global__ void scan1_k(const float* __restrict__ th_p)
{
    const int idx = blockIdx.x * blockDim.x + threadIdx.x;
    const int b = idx >> 9;
    const int h = idx & 511;
    const float th = *th_p;
    const float* zp = g_z1 + (size_t)b * Tt * Hh + h;
    float*       sp = g_s1 + (size_t)b * Tt * Hh + h;

    float m = 0.f;
    #pragma unroll 8
    for (int t = 0; t < Tt; t++) {
        m += zp[(size_t)t * Hh];
        const float thr = m / th - 1.0f;
        sp[(size_t)t * Hh] = (thr >= 0.0f) ? 1.0f : 0.0f;
        if (thr > 0.0f) m -= th;
    }
}

// Layer 2 step (ref): m2 = ((1*m2) + s1@W2^T) + b2  -> bias added AFTER the
// membrane+dot sum, every step. Preserve that exact associativity.
__global__ void scan2_k(const float* __restrict__ th_p,
                        const float* __restrict__ bias,
                        float* __restrict__ out)
{
    const int idx = blockIdx.x * blockDim.x + threadIdx.x;
    const int b = idx >> 9;
    const int h = idx & 511;
    const float th = *th_p;
    const float bi = bias[h];
    const float* yp = g_y2 + (size_t)b * Tt * Hh + h;
    float*       sp = out  + (size_t)b * Tt * Hh + h;

    float m = 0.f;
    #pragma unroll 8
    for (int t = 0; t < Tt; t++) {
        m = (m + yp[(size_t)t * Hh]) + bi;   // ((m + dot) + b) — ref order
        const float thr = m / th - 1.0f;
        sp[(size_t)t * Hh] = (thr >= 0.0f) ? 1.0f : 0.0f;
        if (thr > 0.0f) m -= th;
    }
}

extern "C" void kernel_launch(void* const* d_in, const int* in_sizes, int n_in,
                              void* d_out, int out_size)
{
    const float* x   = (const float*)d_in[0];
    const float* c1w = (const float*)d_in[1];
    const float* c1b = (const float*)d_in[2];
    const float* c2w = (const float*)d_in[3];
    const float* c2b = (const float*)d_in[4];
    const float* th1 = (const float*)d_in[5];
    const float* th2 = (const float*)d_in[6];
    float* out = (float*)d_out;

    extract1_k<<<(Hh*Ii + 255)/256, 256>>>(c1w);
    extract2_k<<<(Hh*Hh + 255)/256, 256>>>(c2w);

    dim3 g(512/64, Mm/128);               // (8, 256)
    sgemm1_k<<<g, 256>>>(x, c1b);
    scan1_k<<<Mm/256, 256>>>(th1);
    sgemm2_k<<<g, 256>>>();
    scan2_k<<<Mm/256, 256>>>(th2, c2b, out);
}

// round 3
// speedup vs baseline: 1.6856x; 1.6856x over previous
#include <cuda_runtime.h>

#define Bb 64
#define Tt 512
#define Ii 256
#define Hh 512
#define Mm (Bb*Tt)   // 32768 rows

__device__ __align__(16) float g_W1[Hh*Ii];
__device__ __align__(16) float g_W2[Hh*Hh];
__device__ __align__(16) float g_z1[Mm*Hh];
__device__ __align__(16) float g_s1[Mm*Hh];
__device__ __align__(16) float g_y2[Mm*Hh];

// -------- extract center tap: W[h,i] = conv_w[h,i,1] --------
__global__ void extract1_k(const float* __restrict__ src) {
    int i = blockIdx.x * blockDim.x + threadIdx.x;
    if (i < Hh*Ii) g_W1[i] = src[i*3 + 1];
}
__global__ void extract2_k(const float* __restrict__ src) {
    int i = blockIdx.x * blockDim.x + threadIdx.x;
    if (i < Hh*Hh) g_W2[i] = src[i*3 + 1];
}

// -------- SGEMM: C[M,512] = A[M,K] * B[512,K]^T (+bias) --------
// 128x128 block tile, 256 threads, 8x8 per thread, KT=8,
// gmem->reg prefetch + double-buffered smem (1 sync per K-step).
// Per-element accumulation: single accumulator, ascending k (bitwise-stable).
template<int K, bool ADD_BIAS>
__device__ __forceinline__ void sgemm128(
    const float* __restrict__ A, const float* __restrict__ Bm,
    const float* __restrict__ bias, float* __restrict__ C)
{
    __shared__ float As[2][8][132];
    __shared__ float Bs[2][8][132];

    const int tid = threadIdx.x;
    const int tx  = tid & 15;          // n: 16*8 = 128
    const int ty  = tid >> 4;          // m: 16*8 = 128
    const int m0  = blockIdx.y * 128;
    const int n0  = blockIdx.x * 128;

    const int lr = tid >> 1;           // 0..127
    const int lc = (tid & 1) * 4;      // 0 or 4
    const float* Ap = A  + (size_t)(m0 + lr) * K + lc;
    const float* Bp = Bm + (size_t)(n0 + lr) * K + lc;

    float4 a4 = *(const float4*)Ap;
    float4 b4 = *(const float4*)Bp;
    As[0][lc+0][lr]=a4.x; As[0][lc+1][lr]=a4.y; As[0][lc+2][lr]=a4.z; As[0][lc+3][lr]=a4.w;
    Bs[0][lc+0][lr]=b4.x; Bs[0][lc+1][lr]=b4.y; Bs[0][lc+2][lr]=b4.z; Bs[0][lc+3][lr]=b4.w;
    __syncthreads();

    float acc[8][8];
    #pragma unroll
    for (int i = 0; i < 8; i++)
        #pragma unroll
        for (int j = 0; j < 8; j++) acc[i][j] = 0.f;

    int p = 0;
    for (int k0 = 8; k0 <= K; k0 += 8) {
        const bool more = (k0 < K);
        if (more) { a4 = *(const float4*)(Ap + k0); b4 = *(const float4*)(Bp + k0); }

        #pragma unroll
        for (int k = 0; k < 8; k++) {
            float ra[8], rb[8];
            *(float4*)&ra[0] = *(const float4*)&As[p][k][ty*8];
            *(float4*)&ra[4] = *(const float4*)&As[p][k][ty*8+4];
            *(float4*)&rb[0] = *(const float4*)&Bs[p][k][tx*8];
            *(float4*)&rb[4] = *(const float4*)&Bs[p][k][tx*8+4];
            #pragma unroll
            for (int i = 0; i < 8; i++)
                #pragma unroll
                for (int j = 0; j < 8; j++)
                    acc[i][j] = __fmaf_rn(ra[i], rb[j], acc[i][j]);
        }

        if (more) {
            const int q = p ^ 1;
            As[q][lc+0][lr]=a4.x; As[q][lc+1][lr]=a4.y; As[q][lc+2][lr]=a4.z; As[q][lc+3][lr]=a4.w;
            Bs[q][lc+0][lr]=b4.x; Bs[q][lc+1][lr]=b4.y; Bs[q][lc+2][lr]=b4.z; Bs[q][lc+3][lr]=b4.w;
            __syncthreads();
            p = q;
        }
    }

    #pragma unroll
    for (int i = 0; i < 8; i++) {
        const int m = m0 + ty*8 + i;
        float4 v0, v1;
        v0.x=acc[i][0]; v0.y=acc[i][1]; v0.z=acc[i][2]; v0.w=acc[i][3];
        v1.x=acc[i][4]; v1.y=acc[i][5]; v1.z=acc[i][6]; v1.w=acc[i][7];
        if (ADD_BIAS) {
            const int n = n0 + tx*8;
            v0.x+=bias[n+0]; v0.y+=bias[n+1]; v0.z+=bias[n+2]; v0.w+=bias[n+3];
            v1.x+=bias[n+4]; v1.y+=bias[n+5]; v1.z+=bias[n+6]; v1.w+=bias[n+7];
        }
        float* cp = C + (size_t)m * Hh + n0 + tx*8;
        *(float4*)cp       = v0;
        *(float4*)(cp + 4) = v1;
    }
}

__global__ void __launch_bounds__(256, 2) sgemm1_k(const float* __restrict__ A,
                                                   const float* __restrict__ bias) {
    sgemm128<Ii, true>(A, g_W1, bias, g_z1);
}
__global__ void __launch_bounds__(256, 2) sgemm2_k() {
    sgemm128<Hh, false>(g_s1, g_W2, nullptr, g_y2);
}

// -------- LIF scans: 32768 independent chains over T=512 --------
// th == 1.0f in this dataset: 1/th is exact, m*inv-1 == m/th-1 bitwise.
#define SCH 16   // prefetch chunk depth

template<bool BIAS_EACH_STEP>
__device__ __forceinline__ void scan_body(const float* __restrict__ Z,
                                          float* __restrict__ S,
                                          const float th, const float bi)
{
    const int idx = blockIdx.x * blockDim.x + threadIdx.x;   // 0..32767
    const int b = idx >> 9;
    const int h = idx & 511;
    const float inv = 1.0f / th;
    const float* zp = Z + (size_t)b * Tt * Hh + h;
    float*       sp = S + (size_t)b * Tt * Hh + h;

    float cur[SCH], nxt[SCH];
    #pragma unroll
    for (int u = 0; u < SCH; u++) cur[u] = zp[(size_t)u * Hh];

    float m = 0.f;
    for (int t0 = 0; t0 < Tt; t0 += SCH) {
        if (t0 + SCH < Tt) {
            #pragma unroll
            for (int u = 0; u < SCH; u++) nxt[u] = zp[(size_t)(t0 + SCH + u) * Hh];
        }
        #pragma unroll
        for (int u = 0; u < SCH; u++) {
            if (BIAS_EACH_STEP) m = (m + cur[u]) + bi;   // ((m + dot) + b) ref order
            else                m = m + cur[u];
            const float thr = __fmaf_rn(m, inv, -1.0f);
            sp[(size_t)(t0 + u) * Hh] = (thr >= 0.0f) ? 1.0f : 0.0f;
            m = (thr > 0.0f) ? (m - th) : m;             // branchless FSEL
        }
        #pragma unroll
        for (int u = 0; u < SCH; u++) cur[u] = nxt[u];
    }
}

__global__ void __launch_bounds__(64) scan1_k(const float* __restrict__ th_p) {
    scan_body<false>(g_z1, g_s1, *th_p, 0.f);
}
__global__ void __launch_bounds__(64) scan2_k(const float* __restrict__ th_p,
                                              const float* __restrict__ bias,
                                              float* __restrict__ out) {
    const int idx = blockIdx.x * blockDim.x + threadIdx.x;
    scan_body<true>(g_y2, out, *th_p, bias[idx & 511]);
}

extern "C" void kernel_launch(void* const* d_in, const int* in_sizes, int n_in,
                              void* d_out, int out_size)
{
    const float* x   = (const float*)d_in[0];
    const float* c1w = (const float*)d_in[1];
    const float* c1b = (const float*)d_in[2];
    const float* c2w = (const float*)d_in[3];
    const float* c2b = (const float*)d_in[4];
    const float* th1 = (const float*)d_in[5];
    const float* th2 = (const float*)d_in[6];
    float* out = (float*)d_out;

    extract1_k<<<(Hh*Ii + 255)/256, 256>>>(c1w);
    extract2_k<<<(Hh*Hh + 255)/256, 256>>>(c2w);

    dim3 g1(Hh/128, Mm/128);              // (4, 256)
    sgemm1_k<<<g1, 256>>>(x, c1b);
    scan1_k<<<Mm/64, 64>>>(th1);
    sgemm2_k<<<g1, 256>>>();
    scan2_k<<<Mm/64, 64>>>(th2, c2b, out);
}